// round 2
// baseline (speedup 1.0000x reference)
#include <cuda_runtime.h>

#define Bsz 32
#define IC 256
#define OC 256
#define HW 56
#define NUM 64
#define WELEMS (OC * IC * 9)          // 589824 weight elements per sample
#define ICB 8                         // input channels per smem stage

// Per-sample synthesized weights: [B][OC][IC][3][3]  (75.5 MB scratch)
__device__ float g_wsyn[(size_t)Bsz * WELEMS];

// ---------------------------------------------------------------------------
// Kernel 1: weight synthesis  w[b][o] = sum_n se[b][n] * W[o][n]
// One thread per o, computing all 32 batches; W row (64 floats) cached in regs.
// ---------------------------------------------------------------------------
__global__ void synth_kernel(const float* __restrict__ se,
                             const float* __restrict__ Wt) {
    __shared__ float s_se[Bsz * NUM];
    for (int i = threadIdx.x; i < Bsz * NUM; i += blockDim.x) s_se[i] = se[i];
    __syncthreads();

    int o = blockIdx.x * blockDim.x + threadIdx.x;
    if (o >= WELEMS) return;

    float4 wv[16];
    const float4* wp = reinterpret_cast<const float4*>(Wt + (size_t)o * NUM);
    #pragma unroll
    for (int i = 0; i < 16; i++) wv[i] = wp[i];

    #pragma unroll 4
    for (int b = 0; b < Bsz; b++) {
        const float4* sp = reinterpret_cast<const float4*>(s_se + b * NUM);
        float acc = 0.f;
        #pragma unroll
        for (int i = 0; i < 16; i++) {
            float4 s = sp[i];
            acc += wv[i].x * s.x + wv[i].y * s.y + wv[i].z * s.z + wv[i].w * s.w;
        }
        g_wsyn[(size_t)b * WELEMS + o] = acc;
    }
}

// ---------------------------------------------------------------------------
// Kernel 2: direct 3x3 conv, stride 1, pad 1, per-sample weights.
// Block: 128 threads -> 64 OC x (8x8 pixels) tile of one sample.
// Thread: 4 OC x (4 wide x 2 tall) = 32 accumulators.
// Per ic: 24 input LDS + 36 weight LDS -> 288 FMA  (ratio 4.8, FMA-bound)
// ---------------------------------------------------------------------------
__global__ __launch_bounds__(128)
void conv_kernel(const float* __restrict__ in,
                 const float* __restrict__ bias,
                 float* __restrict__ out) {
    __shared__ float s_in[ICB][10][11];   // halo tile, row padded 10->11 (bank-conflict-free)
    __shared__ float s_w[ICB][64][9];

    int tid = threadIdx.x;
    int ocT = tid >> 3;                   // 0..15 (x4 OC each)
    int pxT = tid & 7;                    // 0..7  (x8 pixels each)
    int x0 = (pxT & 1) * 4;               // 2 threads across x, 4 px each
    int y0 = (pxT >> 1) * 2;              // 4 threads across y, 2 rows each

    int tileId = blockIdx.x;              // 0..48
    int tx = (tileId % 7) * 8;
    int ty = (tileId / 7) * 8;
    int ocg = blockIdx.y;                 // 0..3  (64 OC per group)
    int b   = blockIdx.z;                 // 0..31

    const float* inB = in + (size_t)b * IC * HW * HW;
    const float* wB  = g_wsyn + (size_t)b * WELEMS + (size_t)ocg * 64 * IC * 9;

    float acc[4][8];
    #pragma unroll
    for (int i = 0; i < 4; i++) {
        float bi = bias[ocg * 64 + ocT * 4 + i];
        #pragma unroll
        for (int p = 0; p < 8; p++) acc[i][p] = bi;
    }

    for (int icc = 0; icc < IC; icc += ICB) {
        __syncthreads();
        // stage input tile (with halo, zero-padded at borders)
        for (int idx = tid; idx < ICB * 100; idx += 128) {
            int ic = idx / 100;
            int rem = idx % 100;
            int r = rem / 10, c = rem % 10;
            int gy = ty - 1 + r, gx = tx - 1 + c;
            float v = 0.f;
            if ((unsigned)gy < HW && (unsigned)gx < HW)
                v = inB[((size_t)(icc + ic) * HW + gy) * HW + gx];
            s_in[ic][r][c] = v;
        }
        // stage weights for this ic-chunk (64 oc x 9 taps per ic)
        for (int idx = tid; idx < ICB * 64 * 9; idx += 128) {
            int ic = idx / 576;
            int rem = idx % 576;
            int oc = rem / 9, k = rem % 9;
            s_w[ic][oc][k] = wB[((size_t)oc * IC + (icc + ic)) * 9 + k];
        }
        __syncthreads();

        #pragma unroll
        for (int ic = 0; ic < ICB; ic++) {
            float rin[4][6];
            #pragma unroll
            for (int r = 0; r < 4; r++)
                #pragma unroll
                for (int c = 0; c < 6; c++)
                    rin[r][c] = s_in[ic][y0 + r][x0 + c];

            float rw[4][9];
            #pragma unroll
            for (int i = 0; i < 4; i++)
                #pragma unroll
                for (int k = 0; k < 9; k++)
                    rw[i][k] = s_w[ic][ocT * 4 + i][k];

            #pragma unroll
            for (int i = 0; i < 4; i++)
                #pragma unroll
                for (int pr = 0; pr < 2; pr++)
                    #pragma unroll
                    for (int pc = 0; pc < 4; pc++) {
                        float a = acc[i][pr * 4 + pc];
                        #pragma unroll
                        for (int ky = 0; ky < 3; ky++)
                            #pragma unroll
                            for (int kx = 0; kx < 3; kx++)
                                a += rw[i][ky * 3 + kx] * rin[pr + ky][pc + kx];
                        acc[i][pr * 4 + pc] = a;
                    }
        }
    }

    #pragma unroll
    for (int i = 0; i < 4; i++) {
        int oc = ocg * 64 + ocT * 4 + i;
        #pragma unroll
        for (int pr = 0; pr < 2; pr++) {
            int y = ty + y0 + pr;
            #pragma unroll
            for (int pc = 0; pc < 4; pc++) {
                int x = tx + x0 + pc;
                out[(((size_t)b * OC + oc) * HW + y) * HW + x] = acc[i][pr * 4 + pc];
            }
        }
    }
}

// ---------------------------------------------------------------------------
extern "C" void kernel_launch(void* const* d_in, const int* in_sizes, int n_in,
                              void* d_out, int out_size) {
    const float* inputs = (const float*)d_in[0];   // [32,256,56,56]
    const float* se     = (const float*)d_in[1];   // [32,64]
    const float* weight = (const float*)d_in[2];   // [589824,64]
    const float* bias   = (const float*)d_in[3];   // [256]
    float* out = (float*)d_out;                    // [32,256,56,56]

    synth_kernel<<<(WELEMS + 255) / 256, 256>>>(se, weight);

    dim3 grid(49, 4, Bsz);
    conv_kernel<<<grid, 128>>>(inputs, bias, out);
}

// round 5
// speedup vs baseline: 3.2404x; 3.2404x over previous
#include <cuda_runtime.h>
#include <cuda_bf16.h>
#include <cstdint>

#define Bn 32
#define HWn 56
#define NPX 3136

// staged weights: [b][ocg2][chunk16] blocks of [hl2][tap9][ocl128][icl16] bf16 (pre-swizzled)
__device__ __nv_bfloat16 g_wB[(size_t)Bn * 2 * 16 * 36864];
// staged input: [b][yslot58][xslot64][ic256] bf16, zero-padded borders, ic^8 pre-swizzle per xslot&4
__device__ __nv_bfloat16 g_xh[(size_t)Bn * 58 * 64 * 256];
__device__ __nv_bfloat16 g_xl[(size_t)Bn * 58 * 64 * 256];

static __device__ __forceinline__ uint32_t smem_u32(const void* p) {
    uint32_t a;
    asm("{ .reg .u64 t; cvta.to.shared.u64 t, %1; cvt.u32.u64 %0, t; }" : "=r"(a) : "l"(p));
    return a;
}
static __device__ __forceinline__ void cp16(uint32_t dst, const void* src) {
    asm volatile("cp.async.cg.shared.global [%0], [%1], 16;" :: "r"(dst), "l"(src));
}
static __device__ __forceinline__ void cp_commit() {
    asm volatile("cp.async.commit_group;" ::: "memory");
}
static __device__ __forceinline__ void ldsm4(uint32_t* r, uint32_t a) {
    asm volatile("ldmatrix.sync.aligned.m8n8.x4.shared.b16 {%0,%1,%2,%3}, [%4];"
                 : "=r"(r[0]), "=r"(r[1]), "=r"(r[2]), "=r"(r[3]) : "r"(a));
}
static __device__ __forceinline__ void mma(float* c, const uint32_t* a, uint32_t b0, uint32_t b1) {
    asm volatile("mma.sync.aligned.m16n8k16.row.col.f32.bf16.bf16.f32 "
                 "{%0,%1,%2,%3}, {%4,%5,%6,%7}, {%8,%9}, {%0,%1,%2,%3};"
                 : "+f"(c[0]), "+f"(c[1]), "+f"(c[2]), "+f"(c[3])
                 : "r"(a[0]), "r"(a[1]), "r"(a[2]), "r"(a[3]), "r"(b0), "r"(b1));
}
static __device__ __forceinline__ void split_bf16(float v, unsigned short& h, unsigned short& l) {
    __nv_bfloat16 hb = __float2bfloat16_rn(v);
    float r = v - __bfloat162float(hb);
    h = __bfloat16_as_ushort(hb);
    l = __bfloat16_as_ushort(__float2bfloat16_rn(r));
}

// ---------------------------------------------------------------------------
// Kernel 1: weight synthesis directly into staged bf16 hi/lo layout
// ---------------------------------------------------------------------------
__global__ __launch_bounds__(256)
void synth_kernel(const float* __restrict__ se, const float* __restrict__ Wt) {
    __shared__ float s_se[Bn * 64];
    for (int i = threadIdx.x; i < Bn * 64; i += 256) s_se[i] = se[i];
    __syncthreads();

    int t = blockIdx.x * 256 + threadIdx.x;           // 0 .. 589823
    int icl = t & 15;
    int ocl = (t >> 4) & 127;
    int tmp = t >> 11;                                // 0..287
    int tap = tmp % 9;
    int tmp2 = tmp / 9;                               // 0..31
    int chunk = tmp2 & 15;
    int ocg = tmp2 >> 4;

    int oc = ocg * 128 + ocl;
    int ic = chunk * 16 + icl;
    size_t o = ((size_t)oc * 256 + ic) * 9 + tap;

    float4 wv[16];
    const float4* wp = reinterpret_cast<const float4*>(Wt + o * 64);
    #pragma unroll
    for (int i = 0; i < 16; i++) wv[i] = wp[i];

    int iclS = icl ^ ((ocl & 4) ? 8 : 0);
    // per-(b) block index; block = [hl2][tap9][ocl128][icl16] = 36864 elems
    size_t inner_hi = ((size_t)(0 * 9 + tap) * 128 + ocl) * 16 + iclS;
    size_t inner_lo = ((size_t)(1 * 9 + tap) * 128 + ocl) * 16 + iclS;

    #pragma unroll 4
    for (int b = 0; b < Bn; b++) {
        const float4* sp = reinterpret_cast<const float4*>(s_se + b * 64);
        float acc = 0.f;
        #pragma unroll
        for (int i = 0; i < 16; i++) {
            float4 s = sp[i];
            acc += wv[i].x * s.x + wv[i].y * s.y + wv[i].z * s.z + wv[i].w * s.w;
        }
        unsigned short h, l;
        split_bf16(acc, h, l);
        size_t blk = ((size_t)(b * 2 + ocg) * 16 + chunk) * 36864;
        g_wB[blk + inner_hi] = __ushort_as_bfloat16(h);
        g_wB[blk + inner_lo] = __ushort_as_bfloat16(l);
    }
}

// ---------------------------------------------------------------------------
// Kernel 2: input transpose to [b][yslot][xslot][ic] bf16 hi/lo, padded+swizzled
// ---------------------------------------------------------------------------
__global__ __launch_bounds__(256)
void xprep_kernel(const float* __restrict__ in) {
    extern __shared__ float s[];                     // [256][56]
    int ys = blockIdx.x, b = blockIdx.y, t = threadIdx.x;
    size_t obase = ((size_t)b * 58 + ys) * 64 * 256; // elems

    if (ys == 0 || ys == 57) {                       // zero pad rows
        uint4 z = make_uint4(0, 0, 0, 0);
        uint4* ph = reinterpret_cast<uint4*>(g_xh + obase);
        uint4* pl = reinterpret_cast<uint4*>(g_xl + obase);
        for (int i = t; i < 2048; i += 256) { ph[i] = z; pl[i] = z; }
        return;
    }
    int y = ys - 1;
    for (int i = t; i < 256 * 56; i += 256) {
        int ic = i / 56, x = i - ic * 56;
        s[i] = in[((size_t)b * 256 + ic) * NPX + y * 56 + x];
    }
    __syncthreads();

    int xs = t >> 2, icq = t & 3;                    // 64 slots x 4 ic-quarters
    bool real = (xs >= 1 && xs <= 56);
    int xsw = (xs & 4) ? 8 : 0;
    #pragma unroll
    for (int g = 0; g < 8; g++) {                    // 8 ic per uint4 store
        unsigned short hs[8], ls[8];
        #pragma unroll
        for (int j = 0; j < 8; j++) {
            int ic_out = icq * 64 + g * 8 + j;
            int src_ic = ic_out ^ xsw;
            float v = real ? s[src_ic * 56 + (xs - 1)] : 0.f;
            split_bf16(v, hs[j], ls[j]);
        }
        size_t eo = obase + (size_t)xs * 256 + icq * 64 + g * 8;
        *reinterpret_cast<uint4*>(g_xh + eo) = make_uint4(
            (uint32_t)hs[0] | ((uint32_t)hs[1] << 16), (uint32_t)hs[2] | ((uint32_t)hs[3] << 16),
            (uint32_t)hs[4] | ((uint32_t)hs[5] << 16), (uint32_t)hs[6] | ((uint32_t)hs[7] << 16));
        *reinterpret_cast<uint4*>(g_xl + eo) = make_uint4(
            (uint32_t)ls[0] | ((uint32_t)ls[1] << 16), (uint32_t)ls[2] | ((uint32_t)ls[3] << 16),
            (uint32_t)ls[4] | ((uint32_t)ls[5] << 16), (uint32_t)ls[6] | ((uint32_t)ls[7] << 16));
    }
}

// ---------------------------------------------------------------------------
// Kernel 3: implicit-GEMM conv via mma.sync (bf16 3-pass), cp.async pipeline.
// grid (28 pxtile, 2 ocg, 32 b), 224 threads, 180224B dyn smem.
// smem buf: [B: hl2][tap9][oc128][ic16] 73728B | [A: hl2][yr4][slot64][ic16] 16384B
// ---------------------------------------------------------------------------
#define BUFB 90112
#define SMEM_TOTAL (2 * BUFB)

__global__ __launch_bounds__(224, 1)
void conv_kernel(const float* __restrict__ bias, float* __restrict__ out) {
    extern __shared__ char smem[];
    uint32_t sb = smem_u32(smem);
    int t = threadIdx.x, warp = t >> 5, lane = t & 31;
    int tile = blockIdx.x, ocg = blockIdx.y, b = blockIdx.z;
    int yT = tile * 2, p0 = tile * 112;

    // A lane role (per-warp m16 of pixels)
    int pxl = warp * 16 + (lane & 7) + ((lane >> 3) & 1) * 8;  // 0..111
    int yrel = pxl / 56;
    int xx = pxl - yrel * 56;
    uint32_t kh16 = (uint32_t)(lane >> 4) * 16;
    // B lane role
    int oc_lane = (lane & 7) + ((lane >> 4) & 1) * 8;
    uint32_t bsw = ((uint32_t)((lane >> 3) & 1) * 16) ^ (uint32_t)((oc_lane & 4) << 2);

    const char* wsrc = (const char*)g_wB + ((size_t)(b * 2 + ocg) * 16) * 73728;
    const char* xh0 = (const char*)g_xh + ((size_t)b * 58 + yT) * 32768;
    const char* xl0 = (const char*)g_xl + ((size_t)b * 58 + yT) * 32768;

    float acc[8][2][4];
    #pragma unroll
    for (int i = 0; i < 8; i++)
        #pragma unroll
        for (int j = 0; j < 2; j++)
            #pragma unroll
            for (int k = 0; k < 4; k++) acc[i][j][k] = 0.f;

    auto stage = [&](int c, uint32_t bo) {
        const char* wb = wsrc + (size_t)c * 73728;
        for (int i = t; i < 4608; i += 224)
            cp16(sb + bo + i * 16, wb + i * 16);
        for (int i = t; i < 1024; i += 224) {
            int hl = i >> 9, r = i & 511;
            int yr = r >> 7, r2 = r & 127, slot = r2 >> 1, half = r2 & 1;
            const char* src = (hl ? xl0 : xh0) + (size_t)yr * 32768 + slot * 512 + c * 32 + half * 16;
            cp16(sb + bo + 73728 + hl * 8192 + yr * 2048 + slot * 32 + half * 16, src);
        }
    };

    stage(0, 0);
    cp_commit();

    for (int c = 0; c < 16; c++) {
        uint32_t bo = (uint32_t)(c & 1) * BUFB;
        if (c < 15) {
            stage(c + 1, (uint32_t)((c + 1) & 1) * BUFB);
            cp_commit();
            asm volatile("cp.async.wait_group 1;" ::: "memory");
        } else {
            asm volatile("cp.async.wait_group 0;" ::: "memory");
        }
        __syncthreads();

        uint32_t Ab = sb + bo + 73728;
        uint32_t Bb = sb + bo;
        #pragma unroll
        for (int ky = 0; ky < 3; ky++) {
            uint32_t arow = Ab + (uint32_t)(yrel + ky) * 2048;
            #pragma unroll
            for (int kx = 0; kx < 3; kx++) {
                int slot = xx + kx;
                uint32_t aoff = arow + (uint32_t)slot * 32 + (kh16 ^ (uint32_t)((slot & 4) << 2));
                uint32_t ah[4], al[4];
                ldsm4(ah, aoff);
                ldsm4(al, aoff + 8192);
                uint32_t b0a = Bb + (uint32_t)(ky * 3 + kx) * 4096 + (uint32_t)oc_lane * 32 + bsw;
                #pragma unroll
                for (int np = 0; np < 8; np++) {
                    uint32_t bh[4], bl[4];
                    ldsm4(bh, b0a + np * 512);
                    ldsm4(bl, b0a + np * 512 + 36864);
                    mma(acc[np][0], ah, bh[0], bh[1]);
                    mma(acc[np][0], ah, bl[0], bl[1]);
                    mma(acc[np][0], al, bh[0], bh[1]);
                    mma(acc[np][1], ah, bh[2], bh[3]);
                    mma(acc[np][1], ah, bl[2], bl[3]);
                    mma(acc[np][1], al, bh[2], bh[3]);
                }
            }
        }
        __syncthreads();
    }

    // epilogue: transpose through smem for coalesced stores
    float* s_out = reinterpret_cast<float*>(smem);   // [oc128][px112]
    int prow = lane >> 2, pcol = (lane & 3) * 2;
    #pragma unroll
    for (int np = 0; np < 8; np++)
        #pragma unroll
        for (int nt = 0; nt < 2; nt++)
            #pragma unroll
            for (int r = 0; r < 4; r++) {
                int oc = np * 16 + nt * 8 + pcol + (r & 1);
                int px = warp * 16 + prow + (r >> 1) * 8;
                s_out[oc * 112 + px] = acc[np][nt][r];
            }
    __syncthreads();
    for (int i = t; i < 14336; i += 224) {
        int oc = i / 112, px = i - oc * 112;
        float v = s_out[i] + bias[ocg * 128 + oc];
        out[((size_t)b * 256 + ocg * 128 + oc) * NPX + p0 + px] = v;
    }
}

// ---------------------------------------------------------------------------
extern "C" void kernel_launch(void* const* d_in, const int* in_sizes, int n_in,
                              void* d_out, int out_size) {
    const float* inputs = (const float*)d_in[0];   // [32,256,56,56]
    const float* se     = (const float*)d_in[1];   // [32,64]
    const float* weight = (const float*)d_in[2];   // [589824,64]
    const float* bias   = (const float*)d_in[3];   // [256]
    float* out = (float*)d_out;

    cudaFuncSetAttribute(xprep_kernel, cudaFuncAttributeMaxDynamicSharedMemorySize, 57344);
    cudaFuncSetAttribute(conv_kernel, cudaFuncAttributeMaxDynamicSharedMemorySize, SMEM_TOTAL);

    synth_kernel<<<589824 / 256, 256>>>(se, weight);
    xprep_kernel<<<dim3(58, Bn), 256, 57344>>>(inputs);
    conv_kernel<<<dim3(28, 2, Bn), 224, SMEM_TOTAL>>>(bias, out);
}

// round 8
// speedup vs baseline: 3.2423x; 1.0006x over previous
#include <cuda_runtime.h>
#include <cuda_bf16.h>
#include <cstdint>

#define Bn 32
#define HWn 56
#define NPX 3136

// staged weights: [b][ocg2][chunk16] blocks of [hl2][tap9][ocl128][icl16] bf16 (pre-swizzled)
__device__ __nv_bfloat16 g_wB[(size_t)Bn * 2 * 16 * 36864];
// staged input: [b][yslot58][xslot64][ic256] bf16, zero-padded borders, ic^8 pre-swizzle per xslot&4
__device__ __nv_bfloat16 g_xh[(size_t)Bn * 58 * 64 * 256];
__device__ __nv_bfloat16 g_xl[(size_t)Bn * 58 * 64 * 256];

static __device__ __forceinline__ uint32_t smem_u32(const void* p) {
    uint32_t a;
    asm("{ .reg .u64 t; cvta.to.shared.u64 t, %1; cvt.u32.u64 %0, t; }" : "=r"(a) : "l"(p));
    return a;
}
static __device__ __forceinline__ void cp16(uint32_t dst, const void* src) {
    asm volatile("cp.async.cg.shared.global [%0], [%1], 16;" :: "r"(dst), "l"(src));
}
static __device__ __forceinline__ void cp_commit() {
    asm volatile("cp.async.commit_group;" ::: "memory");
}
static __device__ __forceinline__ void ldsm4(uint32_t* r, uint32_t a) {
    asm volatile("ldmatrix.sync.aligned.m8n8.x4.shared.b16 {%0,%1,%2,%3}, [%4];"
                 : "=r"(r[0]), "=r"(r[1]), "=r"(r[2]), "=r"(r[3]) : "r"(a));
}
static __device__ __forceinline__ void mma(float* c, const uint32_t* a, uint32_t b0, uint32_t b1) {
    asm volatile("mma.sync.aligned.m16n8k16.row.col.f32.bf16.bf16.f32 "
                 "{%0,%1,%2,%3}, {%4,%5,%6,%7}, {%8,%9}, {%0,%1,%2,%3};"
                 : "+f"(c[0]), "+f"(c[1]), "+f"(c[2]), "+f"(c[3])
                 : "r"(a[0]), "r"(a[1]), "r"(a[2]), "r"(a[3]), "r"(b0), "r"(b1));
}
static __device__ __forceinline__ void split_bf16(float v, unsigned short& h, unsigned short& l) {
    __nv_bfloat16 hb = __float2bfloat16_rn(v);
    float r = v - __bfloat162float(hb);
    h = __bfloat16_as_ushort(hb);
    l = __bfloat16_as_ushort(__float2bfloat16_rn(r));
}

// ---------------------------------------------------------------------------
// Kernel 1: weight synthesis, coalesced via smem row staging + smem out staging.
// Block = one dest tile: (tap, ocl_hi, chunk, ocg) -> 16 ocl x 16 icl = 256 rows.
// s_rows stride = 68 floats (272B = 17x16B): float4-aligned AND conflict-free
// (16B-unit index = 17*tid + i -> (tid+i) mod 8 covers all units).
// ---------------------------------------------------------------------------
#define SY_SE   0
#define SY_ROWS 8192
#define SY_ST   (SY_ROWS + 256 * 68 * 4)
#define SY_TOTAL (SY_ST + 32768)

__global__ __launch_bounds__(256)
void synth_kernel(const float* __restrict__ se, const float* __restrict__ Wt) {
    extern __shared__ char sy[];
    float* s_se = reinterpret_cast<float*>(sy + SY_SE);
    float* s_rows = reinterpret_cast<float*>(sy + SY_ROWS);
    unsigned short* s_st = reinterpret_cast<unsigned short*>(sy + SY_ST);

    int tid = threadIdx.x;
    int blk = blockIdx.x;                  // 2304 = 9*8*16*2
    int tap = blk % 9; int tmp = blk / 9;
    int ocl_hi = tmp & 7; tmp >>= 3;
    int chunk = tmp & 15; int ocg = tmp >> 4;
    int oc0 = ocg * 128 + ocl_hi * 16, ic0 = chunk * 16;

    for (int i = tid; i < Bn * 64; i += 256) s_se[i] = se[i];
    // stage 256 Wt rows (each 256B) coalesced: 16 lanes x 16B per row segment
    for (int i = tid; i < 4096; i += 256) {
        int seg = i >> 4, part = i & 15;
        size_t o = ((size_t)(oc0 + (seg >> 4)) * 256 + (ic0 + (seg & 15))) * 9 + tap;
        *reinterpret_cast<float4*>(&s_rows[seg * 68 + part * 4]) =
            *reinterpret_cast<const float4*>(Wt + o * 64 + part * 4);
    }
    __syncthreads();

    float4 wv[16];
    #pragma unroll
    for (int i = 0; i < 16; i++)
        wv[i] = *reinterpret_cast<const float4*>(&s_rows[tid * 68 + i * 4]);

    int icl = tid & 15, ocl_l = tid >> 4;
    int iclS = icl ^ ((ocl_l & 4) ? 8 : 0);
    int dsti = ocl_l * 16 + iclS;

    #pragma unroll 4
    for (int b = 0; b < Bn; b++) {
        const float4* sp = reinterpret_cast<const float4*>(s_se + b * 64);
        float acc = 0.f;
        #pragma unroll
        for (int i = 0; i < 16; i++) {
            float4 s = sp[i];
            acc += wv[i].x * s.x + wv[i].y * s.y + wv[i].z * s.z + wv[i].w * s.w;
        }
        unsigned short h, l;
        split_bf16(acc, h, l);
        s_st[(b * 2 + 0) * 256 + dsti] = h;
        s_st[(b * 2 + 1) * 256 + dsti] = l;
    }
    __syncthreads();

    // flush: per (b, hl) one contiguous 512B chunk
    size_t inner0 = (size_t)tap * 2048 + (size_t)ocl_hi * 256;
    for (int i = tid; i < 2048; i += 256) {
        int b = i >> 6, r = i & 63, hl = r >> 5, part = r & 31;
        size_t blko = ((size_t)(b * 2 + ocg) * 16 + chunk) * 36864;
        uint4 v = *reinterpret_cast<const uint4*>(&s_st[(b * 2 + hl) * 256 + part * 8]);
        *reinterpret_cast<uint4*>(&g_wB[blko + inner0 + (size_t)hl * 18432 + part * 8]) = v;
    }
}

// ---------------------------------------------------------------------------
// Kernel 2: input transpose to [b][yslot][xslot][ic] bf16 hi/lo, padded+swizzled
// ---------------------------------------------------------------------------
__global__ __launch_bounds__(256)
void xprep_kernel(const float* __restrict__ in) {
    extern __shared__ float s[];                     // [256][56]
    int ys = blockIdx.x, b = blockIdx.y, t = threadIdx.x;
    size_t obase = ((size_t)b * 58 + ys) * 64 * 256;

    if (ys == 0 || ys == 57) {
        uint4 z = make_uint4(0, 0, 0, 0);
        uint4* ph = reinterpret_cast<uint4*>(g_xh + obase);
        uint4* pl = reinterpret_cast<uint4*>(g_xl + obase);
        for (int i = t; i < 2048; i += 256) { ph[i] = z; pl[i] = z; }
        return;
    }
    int y = ys - 1;
    for (int i = t; i < 256 * 56; i += 256) {
        int ic = i / 56, x = i - ic * 56;
        s[i] = in[((size_t)b * 256 + ic) * NPX + y * 56 + x];
    }
    __syncthreads();

    int xs = t >> 2, icq = t & 3;
    bool real = (xs >= 1 && xs <= 56);
    int xsw = (xs & 4) ? 8 : 0;
    #pragma unroll
    for (int g = 0; g < 8; g++) {
        unsigned short hs[8], ls[8];
        #pragma unroll
        for (int j = 0; j < 8; j++) {
            int ic_out = icq * 64 + g * 8 + j;
            int src_ic = ic_out ^ xsw;
            float v = real ? s[src_ic * 56 + (xs - 1)] : 0.f;
            split_bf16(v, hs[j], ls[j]);
        }
        size_t eo = obase + (size_t)xs * 256 + icq * 64 + g * 8;
        *reinterpret_cast<uint4*>(g_xh + eo) = make_uint4(
            (uint32_t)hs[0] | ((uint32_t)hs[1] << 16), (uint32_t)hs[2] | ((uint32_t)hs[3] << 16),
            (uint32_t)hs[4] | ((uint32_t)hs[5] << 16), (uint32_t)hs[6] | ((uint32_t)hs[7] << 16));
        *reinterpret_cast<uint4*>(g_xl + eo) = make_uint4(
            (uint32_t)ls[0] | ((uint32_t)ls[1] << 16), (uint32_t)ls[2] | ((uint32_t)ls[3] << 16),
            (uint32_t)ls[4] | ((uint32_t)ls[5] << 16), (uint32_t)ls[6] | ((uint32_t)ls[7] << 16));
    }
}

// ---------------------------------------------------------------------------
// Kernel 3: implicit-GEMM conv via mma.sync (bf16 3-pass), cp.async pipeline.
// grid (25 pxtile, 2 ocg, 32 b), 256 threads (8 warps, SMSP-balanced).
// buf: [B: hl2][tap9][oc128][ic16] 73728B | [A: hl2][slot6][xs64][ic16] 24576B
// ---------------------------------------------------------------------------
#define BUFB 98304
#define SMEM_TOTAL (2 * BUFB)

__global__ __launch_bounds__(256, 1)
void conv_kernel(const float* __restrict__ bias, float* __restrict__ out) {
    extern __shared__ char smem[];
    uint32_t sb = smem_u32(smem);
    int t = threadIdx.x, warp = t >> 5, lane = t & 31;
    int tile = blockIdx.x, ocg = blockIdx.y, b = blockIdx.z;
    int p0 = tile * 128;
    int base = p0 / 56; if (base > 52) base = 52;

    // A lane role: per-lane pixel pointer (8 warps x m16 = 128 px slots)
    int pxl = warp * 16 + (lane & 7) + ((lane >> 3) & 1) * 8;   // 0..127
    int pixel = p0 + pxl; if (pixel >= NPX) pixel = p0;
    int yy = pixel / 56;
    int xx = pixel - yy * 56;
    int yrel = yy - base;                                       // 0..3 (tile spans <=4 rows)
    uint32_t kh16 = (uint32_t)(lane >> 4) * 16;
    // B lane role
    int oc_lane = (lane & 7) + ((lane >> 4) & 1) * 8;
    uint32_t bsw = ((uint32_t)((lane >> 3) & 1) * 16) ^ (uint32_t)((oc_lane & 4) << 2);

    const char* wsrc = (const char*)g_wB + ((size_t)(b * 2 + ocg) * 16) * 73728;
    const char* xh0 = (const char*)g_xh + ((size_t)b * 58 + base) * 32768;
    const char* xl0 = (const char*)g_xl + ((size_t)b * 58 + base) * 32768;

    float acc[8][2][4];
    #pragma unroll
    for (int i = 0; i < 8; i++)
        #pragma unroll
        for (int j = 0; j < 2; j++)
            #pragma unroll
            for (int k = 0; k < 4; k++) acc[i][j][k] = 0.f;

    auto stage = [&](int c, uint32_t bo) {
        const char* wb = wsrc + (size_t)c * 73728;
        for (int i = t; i < 4608; i += 256)
            cp16(sb + bo + i * 16, wb + i * 16);
        // A: [hl2][slot6][xs64][32B]
        for (int i = t; i < 1536; i += 256) {
            int slot = i >> 8, j2 = i & 255;
            int hl = j2 >> 7, j = j2 & 127, xs = j >> 1, half = j & 1;
            const char* src = (hl ? xl0 : xh0) + (size_t)slot * 32768 + xs * 512 + c * 32 + half * 16;
            cp16(sb + bo + 73728 + hl * 12288 + slot * 2048 + xs * 32 + half * 16, src);
        }
    };

    stage(0, 0);
    cp_commit();

    for (int c = 0; c < 16; c++) {
        uint32_t bo = (uint32_t)(c & 1) * BUFB;
        if (c < 15) {
            stage(c + 1, (uint32_t)((c + 1) & 1) * BUFB);
            cp_commit();
            asm volatile("cp.async.wait_group 1;" ::: "memory");
        } else {
            asm volatile("cp.async.wait_group 0;" ::: "memory");
        }
        __syncthreads();

        uint32_t Ab = sb + bo + 73728;
        uint32_t Bb = sb + bo;
        #pragma unroll
        for (int ky = 0; ky < 3; ky++) {
            uint32_t arow = Ab + (uint32_t)(yrel + ky) * 2048;
            #pragma unroll
            for (int kx = 0; kx < 3; kx++) {
                int slot = xx + kx;
                uint32_t aoff = arow + (uint32_t)slot * 32 + (kh16 ^ (uint32_t)((slot & 4) << 2));
                uint32_t ah[4], al[4];
                ldsm4(ah, aoff);
                ldsm4(al, aoff + 12288);
                uint32_t b0a = Bb + (uint32_t)(ky * 3 + kx) * 4096 + (uint32_t)oc_lane * 32 + bsw;
                #pragma unroll
                for (int np = 0; np < 8; np++) {
                    uint32_t bh[4], bl[4];
                    ldsm4(bh, b0a + np * 512);
                    ldsm4(bl, b0a + np * 512 + 36864);
                    mma(acc[np][0], ah, bh[0], bh[1]);
                    mma(acc[np][0], ah, bl[0], bl[1]);
                    mma(acc[np][0], al, bh[0], bh[1]);
                    mma(acc[np][1], ah, bh[2], bh[3]);
                    mma(acc[np][1], ah, bl[2], bl[3]);
                    mma(acc[np][1], al, bh[2], bh[3]);
                }
            }
        }
        __syncthreads();
    }

    // epilogue: transpose through smem [oc128][px 128+pad] for coalesced stores
    float* s_out = reinterpret_cast<float*>(smem);
    int prow = lane >> 2, pcol = (lane & 3) * 2;
    #pragma unroll
    for (int np = 0; np < 8; np++)
        #pragma unroll
        for (int nt = 0; nt < 2; nt++)
            #pragma unroll
            for (int r = 0; r < 4; r++) {
                int oc = np * 16 + nt * 8 + pcol + (r & 1);
                int px = warp * 16 + prow + (r >> 1) * 8;
                s_out[oc * 129 + px] = acc[np][nt][r];
            }
    __syncthreads();
    int lim = NPX - p0;
    for (int i = t; i < 16384; i += 256) {
        int oc = i >> 7, px = i & 127;
        if (px < lim) {
            float v = s_out[oc * 129 + px] + bias[ocg * 128 + oc];
            out[((size_t)b * 256 + ocg * 128 + oc) * NPX + p0 + px] = v;
        }
    }
}

// ---------------------------------------------------------------------------
extern "C" void kernel_launch(void* const* d_in, const int* in_sizes, int n_in,
                              void* d_out, int out_size) {
    const float* inputs = (const float*)d_in[0];   // [32,256,56,56]
    const float* se     = (const float*)d_in[1];   // [32,64]
    const float* weight = (const float*)d_in[2];   // [589824,64]
    const float* bias   = (const float*)d_in[3];   // [256]
    float* out = (float*)d_out;

    cudaFuncSetAttribute(synth_kernel, cudaFuncAttributeMaxDynamicSharedMemorySize, SY_TOTAL);
    cudaFuncSetAttribute(xprep_kernel, cudaFuncAttributeMaxDynamicSharedMemorySize, 57344);
    cudaFuncSetAttribute(conv_kernel, cudaFuncAttributeMaxDynamicSharedMemorySize, SMEM_TOTAL);

    synth_kernel<<<2304, 256, SY_TOTAL>>>(se, weight);
    xprep_kernel<<<dim3(58, Bn), 256, 57344>>>(inputs);
    conv_kernel<<<dim3(25, 2, Bn), 256, SMEM_TOTAL>>>(bias, out);
}

// round 9
// speedup vs baseline: 5.8172x; 1.7942x over previous
#include <cuda_runtime.h>
#include <cuda_fp16.h>
#include <cstdint>

#define Bn 32
#define HWn 56
#define NPX 3136

// staged weights: [b][ocg2][chunk16] blocks of [tap9][ocl128][icl16] fp16 (iclS swizzled)
__device__ __half g_wH[(size_t)Bn * 2 * 16 * 18432];
// staged input: [b][yslot58][xslot64][ic256] fp16, zero-padded borders, ic^8 swizzle per xslot&4
__device__ __half g_xH[(size_t)Bn * 58 * 64 * 256];

static __device__ __forceinline__ uint32_t smem_u32(const void* p) {
    uint32_t a;
    asm("{ .reg .u64 t; cvta.to.shared.u64 t, %1; cvt.u32.u64 %0, t; }" : "=r"(a) : "l"(p));
    return a;
}
static __device__ __forceinline__ void cp16(uint32_t dst, const void* src) {
    asm volatile("cp.async.cg.shared.global [%0], [%1], 16;" :: "r"(dst), "l"(src));
}
static __device__ __forceinline__ void cp_commit() {
    asm volatile("cp.async.commit_group;" ::: "memory");
}
static __device__ __forceinline__ void ldsm4(uint32_t* r, uint32_t a) {
    asm volatile("ldmatrix.sync.aligned.m8n8.x4.shared.b16 {%0,%1,%2,%3}, [%4];"
                 : "=r"(r[0]), "=r"(r[1]), "=r"(r[2]), "=r"(r[3]) : "r"(a));
}
static __device__ __forceinline__ void mma(float* c, const uint32_t* a, uint32_t b0, uint32_t b1) {
    asm volatile("mma.sync.aligned.m16n8k16.row.col.f32.f16.f16.f32 "
                 "{%0,%1,%2,%3}, {%4,%5,%6,%7}, {%8,%9}, {%0,%1,%2,%3};"
                 : "+f"(c[0]), "+f"(c[1]), "+f"(c[2]), "+f"(c[3])
                 : "r"(a[0]), "r"(a[1]), "r"(a[2]), "r"(a[3]), "r"(b0), "r"(b1));
}

// ---------------------------------------------------------------------------
// Kernel 1: weight synthesis -> fp16 staged layout, coalesced reads via smem.
// Block = (tap, ocl_hi, chunk, ocg): 16 ocl x 16 icl = 256 Wt rows.
// s_rows stride 68 floats (272B = 17x16B): float4-aligned + conflict-free.
// Direct fp16 stores: 16 lanes write 32B contiguous, 64B per warp.
// ---------------------------------------------------------------------------
#define SY_SE   0
#define SY_ROWS 8192
#define SY_TOTAL (SY_ROWS + 256 * 68 * 4)   /* 77824 */

__global__ __launch_bounds__(256)
void synth_kernel(const float* __restrict__ se, const float* __restrict__ Wt) {
    extern __shared__ char sy[];
    float* s_se = reinterpret_cast<float*>(sy + SY_SE);
    float* s_rows = reinterpret_cast<float*>(sy + SY_ROWS);

    int tid = threadIdx.x;
    int blk = blockIdx.x;                  // 2304 = 9*8*16*2
    int tap = blk % 9; int tmp = blk / 9;
    int ocl_hi = tmp & 7; tmp >>= 3;
    int chunk = tmp & 15; int ocg = tmp >> 4;
    int oc0 = ocg * 128 + ocl_hi * 16, ic0 = chunk * 16;

    for (int i = tid; i < Bn * 64; i += 256) s_se[i] = se[i];
    // stage 256 Wt rows (256B each) coalesced: 16 lanes x 16B per row segment
    for (int i = tid; i < 4096; i += 256) {
        int seg = i >> 4, part = i & 15;
        size_t o = ((size_t)(oc0 + (seg >> 4)) * 256 + (ic0 + (seg & 15))) * 9 + tap;
        *reinterpret_cast<float4*>(&s_rows[seg * 68 + part * 4]) =
            *reinterpret_cast<const float4*>(Wt + o * 64 + part * 4);
    }
    __syncthreads();

    float4 wv[16];
    #pragma unroll
    for (int i = 0; i < 16; i++)
        wv[i] = *reinterpret_cast<const float4*>(&s_rows[tid * 68 + i * 4]);

    int icl = tid & 15, ocl_l = tid >> 4;
    int iclS = icl ^ ((ocl_l & 4) ? 8 : 0);
    size_t inner = (size_t)tap * 2048 + (size_t)(ocl_hi * 16 + ocl_l) * 16 + iclS;

    #pragma unroll 4
    for (int b = 0; b < Bn; b++) {
        const float4* sp = reinterpret_cast<const float4*>(s_se + b * 64);
        float acc = 0.f;
        #pragma unroll
        for (int i = 0; i < 16; i++) {
            float4 s = sp[i];
            acc += wv[i].x * s.x + wv[i].y * s.y + wv[i].z * s.z + wv[i].w * s.w;
        }
        size_t blko = ((size_t)(b * 2 + ocg) * 16 + chunk) * 18432;
        g_wH[blko + inner] = __float2half_rn(acc);
    }
}

// ---------------------------------------------------------------------------
// Kernel 2: input transpose to [b][yslot][xslot][ic] fp16, padded + swizzled
// ---------------------------------------------------------------------------
__global__ __launch_bounds__(256)
void xprep_kernel(const float* __restrict__ in) {
    extern __shared__ float s[];                     // [256][56]
    int ys = blockIdx.x, b = blockIdx.y, t = threadIdx.x;
    size_t obase = ((size_t)b * 58 + ys) * 64 * 256;

    if (ys == 0 || ys == 57) {
        uint4 z = make_uint4(0, 0, 0, 0);
        uint4* ph = reinterpret_cast<uint4*>(g_xH + obase);
        for (int i = t; i < 2048; i += 256) ph[i] = z;
        return;
    }
    int y = ys - 1;
    for (int i = t; i < 256 * 56; i += 256) {
        int ic = i / 56, x = i - ic * 56;
        s[i] = in[((size_t)b * 256 + ic) * NPX + y * 56 + x];
    }
    __syncthreads();

    int xs = t >> 2, icq = t & 3;
    bool real = (xs >= 1 && xs <= 56);
    int xsw = (xs & 4) ? 8 : 0;
    #pragma unroll
    for (int g = 0; g < 8; g++) {
        unsigned short hs[8];
        #pragma unroll
        for (int j = 0; j < 8; j++) {
            int ic_out = icq * 64 + g * 8 + j;
            int src_ic = ic_out ^ xsw;
            float v = real ? s[src_ic * 56 + (xs - 1)] : 0.f;
            hs[j] = __half_as_ushort(__float2half_rn(v));
        }
        size_t eo = obase + (size_t)xs * 256 + icq * 64 + g * 8;
        *reinterpret_cast<uint4*>(g_xH + eo) = make_uint4(
            (uint32_t)hs[0] | ((uint32_t)hs[1] << 16), (uint32_t)hs[2] | ((uint32_t)hs[3] << 16),
            (uint32_t)hs[4] | ((uint32_t)hs[5] << 16), (uint32_t)hs[6] | ((uint32_t)hs[7] << 16));
    }
}

// ---------------------------------------------------------------------------
// Kernel 3: implicit-GEMM conv via mma.sync fp16 single-pass, cp.async pipeline.
// grid (25 pxtile, 2 ocg, 32 b), 256 threads (8 warps).
// buf: [B: tap9][oc128][ic16] 36864B | [A: slot6][xs64][ic16] 12288B
// ---------------------------------------------------------------------------
#define BUFB 49152
#define SMEM_TOTAL (2 * BUFB)

__global__ __launch_bounds__(256, 1)
void conv_kernel(const float* __restrict__ bias, float* __restrict__ out) {
    extern __shared__ char smem[];
    uint32_t sb = smem_u32(smem);
    int t = threadIdx.x, warp = t >> 5, lane = t & 31;
    int tile = blockIdx.x, ocg = blockIdx.y, b = blockIdx.z;
    int p0 = tile * 128;
    int base = p0 / 56; if (base > 52) base = 52;

    // A lane role: per-lane pixel pointer (8 warps x m16 = 128 px slots)
    int pxl = warp * 16 + (lane & 7) + ((lane >> 3) & 1) * 8;   // 0..127
    int pixel = p0 + pxl; if (pixel >= NPX) pixel = p0;
    int yy = pixel / 56;
    int xx = pixel - yy * 56;
    int yrel = yy - base;                                       // 0..3
    uint32_t kh16 = (uint32_t)(lane >> 4) * 16;
    // B lane role
    int oc_lane = (lane & 7) + ((lane >> 4) & 1) * 8;
    uint32_t bsw = ((uint32_t)((lane >> 3) & 1) * 16) ^ (uint32_t)((oc_lane & 4) << 2);

    const char* wsrc = (const char*)g_wH + ((size_t)(b * 2 + ocg) * 16) * 36864;
    const char* xh0 = (const char*)g_xH + ((size_t)b * 58 + base) * 32768;

    float acc[8][2][4];
    #pragma unroll
    for (int i = 0; i < 8; i++)
        #pragma unroll
        for (int j = 0; j < 2; j++)
            #pragma unroll
            for (int k = 0; k < 4; k++) acc[i][j][k] = 0.f;

    auto stage = [&](int c, uint32_t bo) {
        const char* wb = wsrc + (size_t)c * 36864;
        for (int i = t; i < 2304; i += 256)
            cp16(sb + bo + i * 16, wb + i * 16);
        // A: [slot6][xs64][32B]
        for (int i = t; i < 768; i += 256) {
            int slot = i >> 7, j = i & 127, xs = j >> 1, half = j & 1;
            const char* src = xh0 + (size_t)slot * 32768 + xs * 512 + c * 32 + half * 16;
            cp16(sb + bo + 36864 + slot * 2048 + xs * 32 + half * 16, src);
        }
    };

    stage(0, 0);
    cp_commit();

    for (int c = 0; c < 16; c++) {
        uint32_t bo = (uint32_t)(c & 1) * BUFB;
        if (c < 15) {
            stage(c + 1, (uint32_t)((c + 1) & 1) * BUFB);
            cp_commit();
            asm volatile("cp.async.wait_group 1;" ::: "memory");
        } else {
            asm volatile("cp.async.wait_group 0;" ::: "memory");
        }
        __syncthreads();

        uint32_t Ab = sb + bo + 36864;
        uint32_t Bb = sb + bo;
        #pragma unroll
        for (int ky = 0; ky < 3; ky++) {
            uint32_t arow = Ab + (uint32_t)(yrel + ky) * 2048;
            #pragma unroll
            for (int kx = 0; kx < 3; kx++) {
                int slot = xx + kx;
                uint32_t aoff = arow + (uint32_t)slot * 32 + (kh16 ^ (uint32_t)((slot & 4) << 2));
                uint32_t ah[4];
                ldsm4(ah, aoff);
                uint32_t b0a = Bb + (uint32_t)(ky * 3 + kx) * 4096 + (uint32_t)oc_lane * 32 + bsw;
                #pragma unroll
                for (int np = 0; np < 8; np++) {
                    uint32_t bh[4];
                    ldsm4(bh, b0a + np * 512);
                    mma(acc[np][0], ah, bh[0], bh[1]);
                    mma(acc[np][1], ah, bh[2], bh[3]);
                }
            }
        }
        __syncthreads();
    }

    // epilogue: transpose through smem [oc128][px 128+pad] for coalesced stores
    float* s_out = reinterpret_cast<float*>(smem);
    int prow = lane >> 2, pcol = (lane & 3) * 2;
    #pragma unroll
    for (int np = 0; np < 8; np++)
        #pragma unroll
        for (int nt = 0; nt < 2; nt++)
            #pragma unroll
            for (int r = 0; r < 4; r++) {
                int oc = np * 16 + nt * 8 + pcol + (r & 1);
                int px = warp * 16 + prow + (r >> 1) * 8;
                s_out[oc * 129 + px] = acc[np][nt][r];
            }
    __syncthreads();
    int lim = NPX - p0;
    for (int i = t; i < 16384; i += 256) {
        int oc = i >> 7, px = i & 127;
        if (px < lim) {
            float v = s_out[oc * 129 + px] + bias[ocg * 128 + oc];
            out[((size_t)b * 256 + ocg * 128 + oc) * NPX + p0 + px] = v;
        }
    }
}

// ---------------------------------------------------------------------------
extern "C" void kernel_launch(void* const* d_in, const int* in_sizes, int n_in,
                              void* d_out, int out_size) {
    const float* inputs = (const float*)d_in[0];   // [32,256,56,56]
    const float* se     = (const float*)d_in[1];   // [32,64]
    const float* weight = (const float*)d_in[2];   // [589824,64]
    const float* bias   = (const float*)d_in[3];   // [256]
    float* out = (float*)d_out;

    cudaFuncSetAttribute(synth_kernel, cudaFuncAttributeMaxDynamicSharedMemorySize, SY_TOTAL);
    cudaFuncSetAttribute(xprep_kernel, cudaFuncAttributeMaxDynamicSharedMemorySize, 57344);
    cudaFuncSetAttribute(conv_kernel, cudaFuncAttributeMaxDynamicSharedMemorySize, SMEM_TOTAL);

    synth_kernel<<<2304, 256, SY_TOTAL>>>(se, weight);
    xprep_kernel<<<dim3(58, Bn), 256, 57344>>>(inputs);
    conv_kernel<<<dim3(25, 2, Bn), 256, SMEM_TOTAL>>>(bias, out);
}

// round 11
// speedup vs baseline: 7.1626x; 1.2313x over previous
#include <cuda_runtime.h>
#include <cuda_fp16.h>
#include <cstdint>

#define Bn 32
#define HWn 56
#define NPX 3136

// staged weights: [b][ocg2][chunk16] blocks of [tap9][ocl128][icl16] fp16 (iclS swizzled)
__device__ __half g_wH[(size_t)Bn * 2 * 16 * 18432];
// staged input: [b][yslot58][xslot64][ic256] fp16, zero-padded borders, ic^8 swizzle per xslot&4
__device__ __half g_xH[(size_t)Bn * 58 * 64 * 256];

static __device__ __forceinline__ uint32_t smem_u32(const void* p) {
    uint32_t a;
    asm("{ .reg .u64 t; cvta.to.shared.u64 t, %1; cvt.u32.u64 %0, t; }" : "=r"(a) : "l"(p));
    return a;
}
static __device__ __forceinline__ void cp16(uint32_t dst, const void* src) {
    asm volatile("cp.async.cg.shared.global [%0], [%1], 16;" :: "r"(dst), "l"(src));
}
static __device__ __forceinline__ void cp_commit() {
    asm volatile("cp.async.commit_group;" ::: "memory");
}
static __device__ __forceinline__ void ldsm4(uint32_t* r, uint32_t a) {
    asm volatile("ldmatrix.sync.aligned.m8n8.x4.shared.b16 {%0,%1,%2,%3}, [%4];"
                 : "=r"(r[0]), "=r"(r[1]), "=r"(r[2]), "=r"(r[3]) : "r"(a));
}
static __device__ __forceinline__ void mma(float* c, const uint32_t* a, uint32_t b0, uint32_t b1) {
    asm volatile("mma.sync.aligned.m16n8k16.row.col.f32.f16.f16.f32 "
                 "{%0,%1,%2,%3}, {%4,%5,%6,%7}, {%8,%9}, {%0,%1,%2,%3};"
                 : "+f"(c[0]), "+f"(c[1]), "+f"(c[2]), "+f"(c[3])
                 : "r"(a[0]), "r"(a[1]), "r"(a[2]), "r"(a[3]), "r"(b0), "r"(b1));
}

// ---------------------------------------------------------------------------
// Kernel 1: weight synthesis -> fp16 staged layout, coalesced reads via smem.
// Full b-unroll: 32 independent accumulator chains for ILP.
// ---------------------------------------------------------------------------
#define SY_SE   0
#define SY_ROWS 8192
#define SY_TOTAL (SY_ROWS + 256 * 68 * 4)   /* 77824 */

__global__ __launch_bounds__(256, 2)
void synth_kernel(const float* __restrict__ se, const float* __restrict__ Wt) {
    extern __shared__ char sy[];
    float* s_se = reinterpret_cast<float*>(sy + SY_SE);
    float* s_rows = reinterpret_cast<float*>(sy + SY_ROWS);

    int tid = threadIdx.x;
    int blk = blockIdx.x;                  // 2304 = 9*8*16*2
    int tap = blk % 9; int tmp = blk / 9;
    int ocl_hi = tmp & 7; tmp >>= 3;
    int chunk = tmp & 15; int ocg = tmp >> 4;
    int oc0 = ocg * 128 + ocl_hi * 16, ic0 = chunk * 16;

    for (int i = tid; i < Bn * 64; i += 256) s_se[i] = se[i];
    for (int i = tid; i < 4096; i += 256) {
        int seg = i >> 4, part = i & 15;
        size_t o = ((size_t)(oc0 + (seg >> 4)) * 256 + (ic0 + (seg & 15))) * 9 + tap;
        *reinterpret_cast<float4*>(&s_rows[seg * 68 + part * 4]) =
            *reinterpret_cast<const float4*>(Wt + o * 64 + part * 4);
    }
    __syncthreads();

    float4 wv[16];
    #pragma unroll
    for (int i = 0; i < 16; i++)
        wv[i] = *reinterpret_cast<const float4*>(&s_rows[tid * 68 + i * 4]);

    int icl = tid & 15, ocl_l = tid >> 4;
    int iclS = icl ^ ((ocl_l & 4) ? 8 : 0);
    size_t inner = (size_t)tap * 2048 + (size_t)(ocl_hi * 16 + ocl_l) * 16 + iclS;

    #pragma unroll
    for (int b = 0; b < Bn; b++) {
        const float4* sp = reinterpret_cast<const float4*>(s_se + b * 64);
        float acc = 0.f;
        #pragma unroll
        for (int i = 0; i < 16; i++) {
            float4 s = sp[i];
            acc += wv[i].x * s.x + wv[i].y * s.y + wv[i].z * s.z + wv[i].w * s.w;
        }
        size_t blko = ((size_t)(b * 2 + ocg) * 16 + chunk) * 18432;
        g_wH[blko + inner] = __float2half_rn(acc);
    }
}

// ---------------------------------------------------------------------------
// Kernel 2: input transpose to [b][yslot][xslot][ic] fp16, padded + swizzled
// ---------------------------------------------------------------------------
__global__ __launch_bounds__(256)
void xprep_kernel(const float* __restrict__ in) {
    extern __shared__ float s[];                     // [256][56]
    int ys = blockIdx.x, b = blockIdx.y, t = threadIdx.x;
    size_t obase = ((size_t)b * 58 + ys) * 64 * 256;

    if (ys == 0 || ys == 57) {
        uint4 z = make_uint4(0, 0, 0, 0);
        uint4* ph = reinterpret_cast<uint4*>(g_xH + obase);
        for (int i = t; i < 2048; i += 256) ph[i] = z;
        return;
    }
    int y = ys - 1;
    for (int i = t; i < 256 * 56; i += 256) {
        int ic = i / 56, x = i - ic * 56;
        s[i] = in[((size_t)b * 256 + ic) * NPX + y * 56 + x];
    }
    __syncthreads();

    int xs = t >> 2, icq = t & 3;
    bool real = (xs >= 1 && xs <= 56);
    int xsw = (xs & 4) ? 8 : 0;
    #pragma unroll
    for (int g = 0; g < 8; g++) {
        unsigned short hs[8];
        #pragma unroll
        for (int j = 0; j < 8; j++) {
            int ic_out = icq * 64 + g * 8 + j;
            int src_ic = ic_out ^ xsw;
            float v = real ? s[src_ic * 56 + (xs - 1)] : 0.f;
            hs[j] = __half_as_ushort(__float2half_rn(v));
        }
        size_t eo = obase + (size_t)xs * 256 + icq * 64 + g * 8;
        *reinterpret_cast<uint4*>(g_xH + eo) = make_uint4(
            (uint32_t)hs[0] | ((uint32_t)hs[1] << 16), (uint32_t)hs[2] | ((uint32_t)hs[3] << 16),
            (uint32_t)hs[4] | ((uint32_t)hs[5] << 16), (uint32_t)hs[6] | ((uint32_t)hs[7] << 16));
    }
}

// ---------------------------------------------------------------------------
// Kernel 3: implicit-GEMM conv, fp16 mma.sync, m32-per-warp / oc64-per-CTA.
// grid (13 pxtile256, 4 ocq, 32 b), 256 threads, 2 CTAs/SM.
// buf: [B: tap9][oc64][ic16] 18432B | [A: slot8][xs64][ic16] 16384B
// ---------------------------------------------------------------------------
#define BUFB 34816
#define SMEM_TOTAL (2 * BUFB)   /* 69632 */

__global__ __launch_bounds__(256, 2)
void conv_kernel(const float* __restrict__ bias, float* __restrict__ out) {
    extern __shared__ char smem[];
    uint32_t sb = smem_u32(smem);
    int t = threadIdx.x, warp = t >> 5, lane = t & 31;
    int tile = blockIdx.x, ocq = blockIdx.y, b = blockIdx.z;
    int ocg = ocq >> 1, ohalf = ocq & 1;
    int p0 = tile * 256;
    int base = p0 / 56; if (base > 50) base = 50;

    // A lane roles: warp covers 32 px (two m16 fragments)
    int lrow = (lane & 7) + ((lane >> 3) & 1) * 8;
    uint32_t kh16 = (uint32_t)(lane >> 4) * 16;
    int xx[2], yrel[2];
    #pragma unroll
    for (int m = 0; m < 2; m++) {
        int pixel = p0 + warp * 32 + m * 16 + lrow;
        if (pixel >= NPX) pixel = p0;
        int yy = pixel / 56;
        xx[m] = pixel - yy * 56;
        yrel[m] = yy - base;                         // 0..5
    }
    // B lane role
    int oc_lane = (lane & 7) + ((lane >> 4) & 1) * 8;
    uint32_t bsw = ((uint32_t)((lane >> 3) & 1) * 16) ^ (uint32_t)((oc_lane & 4) << 2);

    const char* wsrc = (const char*)g_wH + ((size_t)(b * 2 + ocg) * 16) * 36864;
    const char* xh0 = (const char*)g_xH + ((size_t)b * 58 + base) * 32768;

    float acc[4][2][2][4];                           // [np][nt][m][4]
    #pragma unroll
    for (int i = 0; i < 4; i++)
        #pragma unroll
        for (int j = 0; j < 2; j++)
            #pragma unroll
            for (int m = 0; m < 2; m++)
                #pragma unroll
                for (int k = 0; k < 4; k++) acc[i][j][m][k] = 0.f;

    auto stage = [&](int c, uint32_t bo) {
        const char* wb = wsrc + (size_t)c * 36864;
        // B: 9 taps x 2048B (oc-half of staged tile)
        for (int i = t; i < 1152; i += 256) {
            int tap = i >> 7, off = i & 127;
            cp16(sb + bo + tap * 2048 + off * 16,
                 wb + tap * 4096 + ohalf * 2048 + off * 16);
        }
        // A: 8 slots x 64 xs x 32B
        for (int i = t; i < 1024; i += 256) {
            int slot = i >> 7, j = i & 127, xs = j >> 1, half = j & 1;
            cp16(sb + bo + 18432 + slot * 2048 + xs * 32 + half * 16,
                 xh0 + (size_t)slot * 32768 + xs * 512 + c * 32 + half * 16);
        }
    };

    stage(0, 0);
    cp_commit();

    for (int c = 0; c < 16; c++) {
        uint32_t bo = (uint32_t)(c & 1) * BUFB;
        if (c < 15) {
            stage(c + 1, (uint32_t)((c + 1) & 1) * BUFB);
            cp_commit();
            asm volatile("cp.async.wait_group 1;" ::: "memory");
        } else {
            asm volatile("cp.async.wait_group 0;" ::: "memory");
        }
        __syncthreads();

        uint32_t Ab = sb + bo + 18432;
        uint32_t Bb = sb + bo;
        #pragma unroll
        for (int ky = 0; ky < 3; ky++) {
            #pragma unroll
            for (int kx = 0; kx < 3; kx++) {
                uint32_t a0[4], a1[4];
                {
                    int s0 = xx[0] + kx;
                    uint32_t ao = Ab + (uint32_t)(yrel[0] + ky) * 2048 + (uint32_t)s0 * 32
                                  + (kh16 ^ (uint32_t)((s0 & 4) << 2));
                    ldsm4(a0, ao);
                    int s1 = xx[1] + kx;
                    uint32_t ao1 = Ab + (uint32_t)(yrel[1] + ky) * 2048 + (uint32_t)s1 * 32
                                   + (kh16 ^ (uint32_t)((s1 & 4) << 2));
                    ldsm4(a1, ao1);
                }
                uint32_t b0a = Bb + (uint32_t)(ky * 3 + kx) * 2048 + (uint32_t)oc_lane * 32 + bsw;
                #pragma unroll
                for (int np = 0; np < 4; np++) {
                    uint32_t bh[4];
                    ldsm4(bh, b0a + np * 512);
                    mma(acc[np][0][0], a0, bh[0], bh[1]);
                    mma(acc[np][0][1], a1, bh[0], bh[1]);
                    mma(acc[np][1][0], a0, bh[2], bh[3]);
                    mma(acc[np][1][1], a1, bh[2], bh[3]);
                }
            }
        }
        __syncthreads();
    }

    // epilogue: transpose through smem [oc64][px 256+pad] for coalesced stores
    float* s_out = reinterpret_cast<float*>(smem);
    int prow = lane >> 2, pcol = (lane & 3) * 2;
    #pragma unroll
    for (int np = 0; np < 4; np++)
        #pragma unroll
        for (int nt = 0; nt < 2; nt++)
            #pragma unroll
            for (int m = 0; m < 2; m++)
                #pragma unroll
                for (int r = 0; r < 4; r++) {
                    int oc = np * 16 + nt * 8 + pcol + (r & 1);
                    int px = warp * 32 + m * 16 + prow + ((r >> 1) & 1) * 8;
                    s_out[oc * 257 + px] = acc[np][nt][m][r];
                }
    __syncthreads();
    int lim = NPX - p0;
    for (int i = t; i < 16384; i += 256) {
        int oc = i >> 8, px = i & 255;
        if (px < lim) {
            float v = s_out[oc * 257 + px] + bias[ocq * 64 + oc];
            out[((size_t)b * 256 + ocq * 64 + oc) * NPX + p0 + px] = v;
        }
    }
}

// ---------------------------------------------------------------------------
extern "C" void kernel_launch(void* const* d_in, const int* in_sizes, int n_in,
                              void* d_out, int out_size) {
    const float* inputs = (const float*)d_in[0];   // [32,256,56,56]
    const float* se     = (const float*)d_in[1];   // [32,64]
    const float* weight = (const float*)d_in[2];   // [589824,64]
    const float* bias   = (const float*)d_in[3];   // [256]
    float* out = (float*)d_out;

    cudaFuncSetAttribute(synth_kernel, cudaFuncAttributeMaxDynamicSharedMemorySize, SY_TOTAL);
    cudaFuncSetAttribute(xprep_kernel, cudaFuncAttributeMaxDynamicSharedMemorySize, 57344);
    cudaFuncSetAttribute(conv_kernel, cudaFuncAttributeMaxDynamicSharedMemorySize, SMEM_TOTAL);

    synth_kernel<<<2304, 256, SY_TOTAL>>>(se, weight);
    xprep_kernel<<<dim3(58, Bn), 256, 57344>>>(inputs);
    conv_kernel<<<dim3(13, 4, Bn), 256, SMEM_TOTAL>>>(bias, out);
}

// round 12
// speedup vs baseline: 7.8977x; 1.1026x over previous
#include <cuda_runtime.h>
#include <cuda_fp16.h>
#include <cstdint>

#define Bn 32
#define HWn 56
#define NPX 3136

// staged weights: [b][ocg2][chunk16] blocks of [tap9][ocl128][icl16] fp16 (iclS swizzled)
__device__ __half g_wH[(size_t)Bn * 2 * 16 * 18432];
// staged input: [b][yslot58][xslot64][ic256] fp16, zero-padded borders, ic^8 swizzle per xslot&4
__device__ __half g_xH[(size_t)Bn * 58 * 64 * 256];

static __device__ __forceinline__ uint32_t smem_u32(const void* p) {
    uint32_t a;
    asm("{ .reg .u64 t; cvta.to.shared.u64 t, %1; cvt.u32.u64 %0, t; }" : "=r"(a) : "l"(p));
    return a;
}
static __device__ __forceinline__ void cp16(uint32_t dst, const void* src) {
    asm volatile("cp.async.cg.shared.global [%0], [%1], 16;" :: "r"(dst), "l"(src));
}
static __device__ __forceinline__ void cp_commit() {
    asm volatile("cp.async.commit_group;" ::: "memory");
}
static __device__ __forceinline__ void ldsm4(uint32_t* r, uint32_t a) {
    asm volatile("ldmatrix.sync.aligned.m8n8.x4.shared.b16 {%0,%1,%2,%3}, [%4];"
                 : "=r"(r[0]), "=r"(r[1]), "=r"(r[2]), "=r"(r[3]) : "r"(a));
}
static __device__ __forceinline__ void mma(float* c, const uint32_t* a, uint32_t b0, uint32_t b1) {
    asm volatile("mma.sync.aligned.m16n8k16.row.col.f32.f16.f16.f32 "
                 "{%0,%1,%2,%3}, {%4,%5,%6,%7}, {%8,%9}, {%0,%1,%2,%3};"
                 : "+f"(c[0]), "+f"(c[1]), "+f"(c[2]), "+f"(c[3])
                 : "r"(a[0]), "r"(a[1]), "r"(a[2]), "r"(a[3]), "r"(b0), "r"(b1));
}

// ---------------------------------------------------------------------------
// Kernel 1: weight synthesis as split-fp16 MMA GEMM.
// Block (tap, ocl_hi, chunk, ocg): M=256 Wt rows x K=64 x N=32 batches.
// hi = fp16(64*v), lo = fp16((64*v - hi)*2048); acc1 = hi*hi, acc2 = cross;
// result = (acc1 + acc2/2048)/64  -> ~2^-22 weight error.
// smem: A_hi 32K | A_lo 32K | B_hi 4K | B_lo 4K | s_out 20.5K  = 94208 B
// ---------------------------------------------------------------------------
#define SA_HI 0
#define SA_LO 32768
#define SB_HI 65536
#define SB_LO 69632
#define S_OUT 73728
#define SY_TOTAL (S_OUT + 20480)

__global__ __launch_bounds__(256, 2)
void synth_kernel(const float* __restrict__ se, const float* __restrict__ Wt) {
    extern __shared__ char sy[];
    uint32_t sb = smem_u32(sy);
    unsigned short* s_out16 = reinterpret_cast<unsigned short*>(sy + S_OUT);

    int tid = threadIdx.x, lane = tid & 31, warp = tid >> 5;
    int blk = blockIdx.x;                  // 2304 = 9*8*16*2
    int tap = blk % 9; int tmp = blk / 9;
    int ocl_hi = tmp & 7; tmp >>= 3;
    int chunk = tmp & 15; int ocg = tmp >> 4;

    // --- load se -> B hi/lo smem (swizzled rows of 128B) ---
    {
        int b = tid >> 3, kq = tid & 7;                 // 8 k-elems (16B unit)
        float4 v0 = *reinterpret_cast<const float4*>(se + b * 64 + kq * 8);
        float4 v1 = *reinterpret_cast<const float4*>(se + b * 64 + kq * 8 + 4);
        float vv[8] = {v0.x, v0.y, v0.z, v0.w, v1.x, v1.y, v1.z, v1.w};
        unsigned short hs[8], ls[8];
        #pragma unroll
        for (int j = 0; j < 8; j++) {
            __half h = __float2half_rn(vv[j]);
            float r = (vv[j] - __half2float(h)) * 2048.f;
            hs[j] = __half_as_ushort(h);
            ls[j] = __half_as_ushort(__float2half_rn(r));
        }
        uint32_t addr = (uint32_t)b * 128 + (uint32_t)((kq ^ (b & 7)) * 16);
        *reinterpret_cast<uint4*>(sy + SB_HI + addr) = make_uint4(
            (uint32_t)hs[0] | ((uint32_t)hs[1] << 16), (uint32_t)hs[2] | ((uint32_t)hs[3] << 16),
            (uint32_t)hs[4] | ((uint32_t)hs[5] << 16), (uint32_t)hs[6] | ((uint32_t)hs[7] << 16));
        *reinterpret_cast<uint4*>(sy + SB_LO + addr) = make_uint4(
            (uint32_t)ls[0] | ((uint32_t)ls[1] << 16), (uint32_t)ls[2] | ((uint32_t)ls[3] << 16),
            (uint32_t)ls[4] | ((uint32_t)ls[5] << 16), (uint32_t)ls[6] | ((uint32_t)ls[7] << 16));
    }

    // --- gather Wt rows -> A hi/lo smem (scaled x64), swizzled 128B rows ---
    for (int i = tid; i < 4096; i += 256) {
        int m = i >> 4, part = i & 15;                  // row, 16B source segment
        size_t o = ((size_t)(ocg * 128 + ocl_hi * 16 + (m >> 4)) * 256
                    + chunk * 16 + (m & 15)) * 9 + tap;
        float4 v = *reinterpret_cast<const float4*>(Wt + o * 64 + part * 4);
        float vv[4] = {v.x, v.y, v.z, v.w};
        unsigned short hs[4], ls[4];
        #pragma unroll
        for (int j = 0; j < 4; j++) {
            float s = vv[j] * 64.f;
            __half h = __float2half_rn(s);
            float r = (s - __half2float(h)) * 2048.f;
            hs[j] = __half_as_ushort(h);
            ls[j] = __half_as_ushort(__float2half_rn(r));
        }
        uint32_t addr = (uint32_t)m * 128 + (uint32_t)((((part >> 1) ^ (m & 7)) * 16) + (part & 1) * 8);
        *reinterpret_cast<uint2*>(sy + SA_HI + addr) = make_uint2(
            (uint32_t)hs[0] | ((uint32_t)hs[1] << 16), (uint32_t)hs[2] | ((uint32_t)hs[3] << 16));
        *reinterpret_cast<uint2*>(sy + SA_LO + addr) = make_uint2(
            (uint32_t)ls[0] | ((uint32_t)ls[1] << 16), (uint32_t)ls[2] | ((uint32_t)ls[3] << 16));
    }
    __syncthreads();

    // --- MMA: warp handles m-tiles {2w, 2w+1}, full N=32 ---
    float acc1[2][4][4], acc2[2][4][4];
    #pragma unroll
    for (int q = 0; q < 2; q++)
        #pragma unroll
        for (int n = 0; n < 4; n++)
            #pragma unroll
            for (int k = 0; k < 4; k++) { acc1[q][n][k] = 0.f; acc2[q][n][k] = 0.f; }

    int a_ml = (lane & 7) + ((lane >> 3) & 1) * 8;      // row-within-m16
    int a_kh = lane >> 4;                               // k-half
    int b_bl = (lane & 7) + ((lane >> 4) & 1) * 8;      // b-row within pair
    int b_kh = (lane >> 3) & 1;

    #pragma unroll
    for (int kt = 0; kt < 4; kt++) {
        uint32_t Ah[2][4], Al[2][4], Bh[2][4], Bl[2][4];
        #pragma unroll
        for (int q = 0; q < 2; q++) {
            int m_l = (warp * 2 + q) * 16 + a_ml;
            uint32_t addr = (uint32_t)m_l * 128 + (uint32_t)(((kt * 2 + a_kh) ^ (m_l & 7)) * 16);
            ldsm4(Ah[q], sb + SA_HI + addr);
            ldsm4(Al[q], sb + SA_LO + addr);
        }
        #pragma unroll
        for (int pr = 0; pr < 2; pr++) {
            int bl = b_bl + pr * 16;
            uint32_t addr = (uint32_t)bl * 128 + (uint32_t)(((kt * 2 + b_kh) ^ (bl & 7)) * 16);
            ldsm4(Bh[pr], sb + SB_HI + addr);
            ldsm4(Bl[pr], sb + SB_LO + addr);
        }
        #pragma unroll
        for (int q = 0; q < 2; q++)
            #pragma unroll
            for (int pr = 0; pr < 2; pr++)
                #pragma unroll
                for (int sub = 0; sub < 2; sub++) {
                    int nt = pr * 2 + sub;
                    mma(acc1[q][nt], Ah[q], Bh[pr][sub * 2], Bh[pr][sub * 2 + 1]);
                    mma(acc2[q][nt], Ah[q], Bl[pr][sub * 2], Bl[pr][sub * 2 + 1]);
                    mma(acc2[q][nt], Al[q], Bh[pr][sub * 2], Bh[pr][sub * 2 + 1]);
                }
    }

    // --- epilogue: combine, round fp16, stage to s_out[m][b] (stride 40) ---
    const float SC = 4.8828125e-4f, INV = 1.f / 64.f;
    #pragma unroll
    for (int q = 0; q < 2; q++)
        #pragma unroll
        for (int nt = 0; nt < 4; nt++) {
            float v0 = (acc1[q][nt][0] + acc2[q][nt][0] * SC) * INV;
            float v1 = (acc1[q][nt][1] + acc2[q][nt][1] * SC) * INV;
            float v2 = (acc1[q][nt][2] + acc2[q][nt][2] * SC) * INV;
            float v3 = (acc1[q][nt][3] + acc2[q][nt][3] * SC) * INV;
            uint32_t p01 = (uint32_t)__half_as_ushort(__float2half_rn(v0))
                         | ((uint32_t)__half_as_ushort(__float2half_rn(v1)) << 16);
            uint32_t p23 = (uint32_t)__half_as_ushort(__float2half_rn(v2))
                         | ((uint32_t)__half_as_ushort(__float2half_rn(v3)) << 16);
            int m0 = (warp * 2 + q) * 16 + (lane >> 2);
            int bc = nt * 8 + (lane & 3) * 2;
            *reinterpret_cast<uint32_t*>(&s_out16[m0 * 40 + bc]) = p01;
            *reinterpret_cast<uint32_t*>(&s_out16[(m0 + 8) * 40 + bc]) = p23;
        }
    __syncthreads();

    // --- flush: per b, 512B contiguous dest chunk ---
    size_t inner = (size_t)tap * 2048 + (size_t)ocl_hi * 256;
    for (int i = tid; i < 8192; i += 256) {
        int b = i >> 8, dlin = i & 255;
        int ocl = dlin >> 4, iclS = dlin & 15;
        int icl = iclS ^ ((ocl & 4) ? 8 : 0);
        int m = ocl * 16 + icl;
        size_t blko = ((size_t)(b * 2 + ocg) * 16 + chunk) * 18432;
        reinterpret_cast<unsigned short*>(g_wH)[blko + inner + dlin] = s_out16[m * 40 + b];
    }
}

// ---------------------------------------------------------------------------
// Kernel 2: input transpose to [b][yslot][xslot][ic] fp16, padded + swizzled
// ---------------------------------------------------------------------------
__global__ __launch_bounds__(256)
void xprep_kernel(const float* __restrict__ in) {
    extern __shared__ float s[];                     // [256][56]
    int ys = blockIdx.x, b = blockIdx.y, t = threadIdx.x;
    size_t obase = ((size_t)b * 58 + ys) * 64 * 256;

    if (ys == 0 || ys == 57) {
        uint4 z = make_uint4(0, 0, 0, 0);
        uint4* ph = reinterpret_cast<uint4*>(g_xH + obase);
        for (int i = t; i < 2048; i += 256) ph[i] = z;
        return;
    }
    int y = ys - 1;
    for (int i = t; i < 256 * 56; i += 256) {
        int ic = i / 56, x = i - ic * 56;
        s[i] = in[((size_t)b * 256 + ic) * NPX + y * 56 + x];
    }
    __syncthreads();

    int xs = t >> 2, icq = t & 3;
    bool real = (xs >= 1 && xs <= 56);
    int xsw = (xs & 4) ? 8 : 0;
    #pragma unroll
    for (int g = 0; g < 8; g++) {
        unsigned short hs[8];
        #pragma unroll
        for (int j = 0; j < 8; j++) {
            int ic_out = icq * 64 + g * 8 + j;
            int src_ic = ic_out ^ xsw;
            float v = real ? s[src_ic * 56 + (xs - 1)] : 0.f;
            hs[j] = __half_as_ushort(__float2half_rn(v));
        }
        size_t eo = obase + (size_t)xs * 256 + icq * 64 + g * 8;
        *reinterpret_cast<uint4*>(g_xH + eo) = make_uint4(
            (uint32_t)hs[0] | ((uint32_t)hs[1] << 16), (uint32_t)hs[2] | ((uint32_t)hs[3] << 16),
            (uint32_t)hs[4] | ((uint32_t)hs[5] << 16), (uint32_t)hs[6] | ((uint32_t)hs[7] << 16));
    }
}

// ---------------------------------------------------------------------------
// Kernel 3: implicit-GEMM conv, fp16 mma.sync, m32-per-warp / oc64-per-CTA.
// grid (13 pxtile256, 4 ocq, 32 b), 256 threads, 2 CTAs/SM.  (unchanged)
// ---------------------------------------------------------------------------
#define BUFB 34816
#define SMEM_TOTAL (2 * BUFB)   /* 69632 */

__global__ __launch_bounds__(256, 2)
void conv_kernel(const float* __restrict__ bias, float* __restrict__ out) {
    extern __shared__ char smem[];
    uint32_t sb = smem_u32(smem);
    int t = threadIdx.x, warp = t >> 5, lane = t & 31;
    int tile = blockIdx.x, ocq = blockIdx.y, b = blockIdx.z;
    int ocg = ocq >> 1, ohalf = ocq & 1;
    int p0 = tile * 256;
    int base = p0 / 56; if (base > 50) base = 50;

    int lrow = (lane & 7) + ((lane >> 3) & 1) * 8;
    uint32_t kh16 = (uint32_t)(lane >> 4) * 16;
    int xx[2], yrel[2];
    #pragma unroll
    for (int m = 0; m < 2; m++) {
        int pixel = p0 + warp * 32 + m * 16 + lrow;
        if (pixel >= NPX) pixel = p0;
        int yy = pixel / 56;
        xx[m] = pixel - yy * 56;
        yrel[m] = yy - base;
    }
    int oc_lane = (lane & 7) + ((lane >> 4) & 1) * 8;
    uint32_t bsw = ((uint32_t)((lane >> 3) & 1) * 16) ^ (uint32_t)((oc_lane & 4) << 2);

    const char* wsrc = (const char*)g_wH + ((size_t)(b * 2 + ocg) * 16) * 36864;
    const char* xh0 = (const char*)g_xH + ((size_t)b * 58 + base) * 32768;

    float acc[4][2][2][4];
    #pragma unroll
    for (int i = 0; i < 4; i++)
        #pragma unroll
        for (int j = 0; j < 2; j++)
            #pragma unroll
            for (int m = 0; m < 2; m++)
                #pragma unroll
                for (int k = 0; k < 4; k++) acc[i][j][m][k] = 0.f;

    auto stage = [&](int c, uint32_t bo) {
        const char* wb = wsrc + (size_t)c * 36864;
        for (int i = t; i < 1152; i += 256) {
            int tap = i >> 7, off = i & 127;
            cp16(sb + bo + tap * 2048 + off * 16,
                 wb + tap * 4096 + ohalf * 2048 + off * 16);
        }
        for (int i = t; i < 1024; i += 256) {
            int slot = i >> 7, j = i & 127, xs = j >> 1, half = j & 1;
            cp16(sb + bo + 18432 + slot * 2048 + xs * 32 + half * 16,
                 xh0 + (size_t)slot * 32768 + xs * 512 + c * 32 + half * 16);
        }
    };

    stage(0, 0);
    cp_commit();

    for (int c = 0; c < 16; c++) {
        uint32_t bo = (uint32_t)(c & 1) * BUFB;
        if (c < 15) {
            stage(c + 1, (uint32_t)((c + 1) & 1) * BUFB);
            cp_commit();
            asm volatile("cp.async.wait_group 1;" ::: "memory");
        } else {
            asm volatile("cp.async.wait_group 0;" ::: "memory");
        }
        __syncthreads();

        uint32_t Ab = sb + bo + 18432;
        uint32_t Bb = sb + bo;
        #pragma unroll
        for (int ky = 0; ky < 3; ky++) {
            #pragma unroll
            for (int kx = 0; kx < 3; kx++) {
                uint32_t a0[4], a1[4];
                {
                    int s0 = xx[0] + kx;
                    uint32_t ao = Ab + (uint32_t)(yrel[0] + ky) * 2048 + (uint32_t)s0 * 32
                                  + (kh16 ^ (uint32_t)((s0 & 4) << 2));
                    ldsm4(a0, ao);
                    int s1 = xx[1] + kx;
                    uint32_t ao1 = Ab + (uint32_t)(yrel[1] + ky) * 2048 + (uint32_t)s1 * 32
                                   + (kh16 ^ (uint32_t)((s1 & 4) << 2));
                    ldsm4(a1, ao1);
                }
                uint32_t b0a = Bb + (uint32_t)(ky * 3 + kx) * 2048 + (uint32_t)oc_lane * 32 + bsw;
                #pragma unroll
                for (int np = 0; np < 4; np++) {
                    uint32_t bh[4];
                    ldsm4(bh, b0a + np * 512);
                    mma(acc[np][0][0], a0, bh[0], bh[1]);
                    mma(acc[np][0][1], a1, bh[0], bh[1]);
                    mma(acc[np][1][0], a0, bh[2], bh[3]);
                    mma(acc[np][1][1], a1, bh[2], bh[3]);
                }
            }
        }
        __syncthreads();
    }

    float* s_out = reinterpret_cast<float*>(smem);
    int prow = lane >> 2, pcol = (lane & 3) * 2;
    #pragma unroll
    for (int np = 0; np < 4; np++)
        #pragma unroll
        for (int nt = 0; nt < 2; nt++)
            #pragma unroll
            for (int m = 0; m < 2; m++)
                #pragma unroll
                for (int r = 0; r < 4; r++) {
                    int oc = np * 16 + nt * 8 + pcol + (r & 1);
                    int px = warp * 32 + m * 16 + prow + ((r >> 1) & 1) * 8;
                    s_out[oc * 257 + px] = acc[np][nt][m][r];
                }
    __syncthreads();
    int lim = NPX - p0;
    for (int i = t; i < 16384; i += 256) {
        int oc = i >> 8, px = i & 255;
        if (px < lim) {
            float v = s_out[oc * 257 + px] + bias[ocq * 64 + oc];
            out[((size_t)b * 256 + ocq * 64 + oc) * NPX + p0 + px] = v;
        }
    }
}

// ---------------------------------------------------------------------------
extern "C" void kernel_launch(void* const* d_in, const int* in_sizes, int n_in,
                              void* d_out, int out_size) {
    const float* inputs = (const float*)d_in[0];   // [32,256,56,56]
    const float* se     = (const float*)d_in[1];   // [32,64]
    const float* weight = (const float*)d_in[2];   // [589824,64]
    const float* bias   = (const float*)d_in[3];   // [256]
    float* out = (float*)d_out;

    cudaFuncSetAttribute(synth_kernel, cudaFuncAttributeMaxDynamicSharedMemorySize, SY_TOTAL);
    cudaFuncSetAttribute(xprep_kernel, cudaFuncAttributeMaxDynamicSharedMemorySize, 57344);
    cudaFuncSetAttribute(conv_kernel, cudaFuncAttributeMaxDynamicSharedMemorySize, SMEM_TOTAL);

    synth_kernel<<<2304, 256, SY_TOTAL>>>(se, weight);
    xprep_kernel<<<dim3(58, Bn), 256, 57344>>>(inputs);
    conv_kernel<<<dim3(13, 4, Bn), 256, SMEM_TOTAL>>>(bias, out);
}